// round 11
// baseline (speedup 1.0000x reference)
#include <cuda_runtime.h>
#include <cuda_bf16.h>

// Seq2SeqLoss: label-smoothed weighted cross-entropy, mean over masked rows.
// Harness canonical dtypes:
//   [0] outputs  f32 [B*S*C] = 131072000
//   [1] gold     i32 [B*S]   = 4096
//   [2] mask     i32 [B*S]   = 4096
//   [3] weight   f32 [C]     = 32000
// output: f32 scalar
//
// Sum factorization: with lse_r = log(sum_c exp(x_rc)), dd_r = sum_c w_c x_rc,
//   sum_r loss_r = uniform*(sumW*Σlse − Σdd) + (conf−uniform)*Σ w_g (lse − x_g)
//
// R10 ncu: DRAM 74%, issue 64%, occ 89% — gap explained by wave quantization
// (grid 4104 / 1184 concurrent = 3.47 waves, paying 4 → ~13% waste).
// R11: one CTA per HALF-row → grid 8200 = 6.93 waves, pay 7 → ~1% waste.
// Halves combine through per-row RED slots + acq_rel counter (no fences:
// gpu-scope fence = CCTL.IVALL = L1 flush on sm_103a).

#define SMOOTHING 0.1f
#define EPSILON   1e-8f
#define SUMW_CTAS 8
#define MAX_ROWS  8192

__device__ float        g_row_s[MAX_ROWS];   // per-row sum-exp partials
__device__ float        g_row_d[MAX_ROWS];   // per-row dot partials
__device__ unsigned int g_row_cnt[MAX_ROWS]; // per-row arrival counter
__device__ float        g_sumw;
__device__ float        g_lse_acc;
__device__ float        g_dot_acc;
__device__ float        g_gold_acc;
__device__ float        g_mask_acc;
__device__ unsigned int g_done;

// All-FMA exp (no MUFU): exp(x) = 2^(x*log2e), magic-number round,
// degree-5 poly for 2^f on [-0.5,0.5] (rel err ~2.4e-6), exponent splice.
__device__ __forceinline__ float fexp(float x) {
    float t = x * 1.4426950408889634f;
    t = fminf(fmaxf(t, -126.0f), 126.0f);
    float r = t + 12582912.0f;
    int   eb = __float_as_int(r) << 23;
    float nf = r - 12582912.0f;
    float f  = t - nf;
    float p  = 1.3333558146428443e-3f;
    p = fmaf(p, f, 9.6181291076284772e-3f);
    p = fmaf(p, f, 5.5504108664821580e-2f);
    p = fmaf(p, f, 2.4022650695910072e-1f);
    p = fmaf(p, f, 6.9314718055994531e-1f);
    p = fmaf(p, f, 1.0f);
    return __int_as_float(__float_as_int(p) + eb);
}

__device__ __forceinline__ float warp_sum(float v) {
    #pragma unroll
    for (int o = 16; o > 0; o >>= 1) v += __shfl_xor_sync(0xffffffffu, v, o);
    return v;
}

// acq_rel counter bump: release orders this thread's prior REDs; acquire on
// the winning bump makes the peer's REDs visible. No L1 flush.
__device__ __forceinline__ unsigned int atom_inc_acqrel(unsigned int* p) {
    unsigned int old;
    asm volatile("atom.acq_rel.gpu.global.add.u32 %0, [%1], 1;"
                 : "=r"(old) : "l"(p) : "memory");
    return old;
}

__device__ __forceinline__ void arrive_and_maybe_finalize(
    float* __restrict__ out, int C, unsigned int total_ctas)
{
    unsigned int prev = atom_inc_acqrel(&g_done);
    if (prev == total_ctas - 1u) {
        float sumw = __ldcg(&g_sumw);
        float lse  = __ldcg(&g_lse_acc);
        float dot  = __ldcg(&g_dot_acc);
        float gld  = __ldcg(&g_gold_acc);
        float msk  = __ldcg(&g_mask_acc);

        const float uniform = SMOOTHING / (float)(C - 1);
        const float conf    = 1.0f - SMOOTHING;
        const float cmu     = conf - uniform;
        float loss_sum = uniform * fmaf(sumw, lse, -dot) + cmu * gld;
        out[0] = loss_sum / (msk + EPSILON);

        __stcg(&g_sumw, 0.0f);
        __stcg(&g_lse_acc, 0.0f);
        __stcg(&g_dot_acc, 0.0f);
        __stcg(&g_gold_acc, 0.0f);
        __stcg(&g_mask_acc, 0.0f);
        unsigned int z = 0u;
        asm volatile("st.global.cg.u32 [%0], %1;" :: "l"(&g_done), "r"(z) : "memory");
    }
}

// Grid = 2N + SUMW_CTAS.
// CTAs [0, 2N):    half-row each — proven streaming loop on HALF_C4 float4s,
//                  per-row combine; second arriver finishes the row.
// CTAs [2N, +8):   sum a slice of weight into g_sumw (in the shadow).
__global__ __launch_bounds__(256) void row_loss_kernel(
    const float* __restrict__ logits,
    const int*   __restrict__ gold,
    const int*   __restrict__ mask,
    const float* __restrict__ weight,
    float* __restrict__ out,
    int C4, int C, int N)
{
    const int bid = blockIdx.x;
    const float4* wp = reinterpret_cast<const float4*>(weight);
    const unsigned int total_ctas = (unsigned int)(2 * N + SUMW_CTAS);
    const int HALF_C4 = C4 >> 1;

    if (bid >= 2 * N) {
        // ---- sumW slice CTA ----
        const int slice = bid - 2 * N;
        const int per   = (C4 + SUMW_CTAS - 1) / SUMW_CTAS;
        const int lo    = slice * per;
        const int hi    = min(lo + per, C4);
        float w = 0.0f;
        for (int i = lo + threadIdx.x; i < hi; i += 256) {
            float4 v = __ldg(wp + i);
            w += v.x + v.y + v.z + v.w;
        }
        __shared__ float shw[8];
        w = warp_sum(w);
        if ((threadIdx.x & 31) == 0) shw[threadIdx.x >> 5] = w;
        __syncthreads();
        if (threadIdx.x == 0) {
            float ww = 0.0f;
            #pragma unroll
            for (int k = 0; k < 8; k++) ww += shw[k];
            atomicAdd(&g_sumw, ww);
            arrive_and_maybe_finalize(out, C, total_ctas);
        }
        return;
    }

    // ---- half-row CTA: streaming loop body identical to the proven version ----
    const int row  = bid >> 1;
    const int half = bid & 1;
    const float4* lp = reinterpret_cast<const float4*>(logits)
                     + (size_t)row * C4 + (size_t)half * HALF_C4;
    const float4* wh = wp + half * HALF_C4;

    float s = 0.0f, d = 0.0f;
    #pragma unroll 4
    for (int i = threadIdx.x; i < HALF_C4; i += 256) {
        float4 x = __ldcs(lp + i);
        float4 w = __ldg(wh + i);
        d = fmaf(x.x, w.x, d);
        d = fmaf(x.y, w.y, d);
        d = fmaf(x.z, w.z, d);
        d = fmaf(x.w, w.w, d);
        s += fexp(x.x);
        s += fexp(x.y);
        s += fexp(x.z);
        s += fexp(x.w);
    }

    __shared__ float sh_s[8], sh_d[8];
    s = warp_sum(s);
    d = warp_sum(d);
    const int wid = threadIdx.x >> 5;
    const int lid = threadIdx.x & 31;
    if (lid == 0) { sh_s[wid] = s; sh_d[wid] = d; }
    __syncthreads();

    if (threadIdx.x == 0) {
        float ss = 0.0f, dd = 0.0f;
        #pragma unroll
        for (int k = 0; k < 8; k++) { ss += sh_s[k]; dd += sh_d[k]; }

        // Per-row combine: REDs, then acq_rel arrival; second arriver owns row.
        atomicAdd(&g_row_s[row], ss);
        atomicAdd(&g_row_d[row], dd);
        unsigned int prev = atom_inc_acqrel(&g_row_cnt[row]);
        if (prev == 1u) {
            float stot = __ldcg(&g_row_s[row]);
            float dtot = __ldcg(&g_row_d[row]);
            // reset row slots for next graph replay
            __stcg(&g_row_s[row], 0.0f);
            __stcg(&g_row_d[row], 0.0f);
            unsigned int z = 0u;
            asm volatile("st.global.cg.u32 [%0], %1;" :: "l"(&g_row_cnt[row]), "r"(z) : "memory");

            if (mask[row] != 0) {
                int   g   = gold[row];
                float xg  = __ldg(logits + (size_t)row * C + (size_t)g);
                float wg  = __ldg(weight + g);
                float lse = logf(stot);

                atomicAdd(&g_lse_acc,  lse);
                atomicAdd(&g_dot_acc,  dtot);
                atomicAdd(&g_gold_acc, wg * (lse - xg));
                atomicAdd(&g_mask_acc, 1.0f);
            }
        }
        arrive_and_maybe_finalize(out, C, total_ctas);
    }
}

extern "C" void kernel_launch(void* const* d_in, const int* in_sizes, int n_in,
                              void* d_out, int out_size)
{
    const float* logits = (const float*)d_in[0];
    const int*   gold   = (const int*)d_in[1];
    const int*   mask   = (const int*)d_in[2];
    const float* weight = (const float*)d_in[3];
    float*       out    = (float*)d_out;

    const int N = in_sizes[1];     // B*S rows
    const int C = in_sizes[3];     // classes
    const int C4 = C / 4;

    row_loss_kernel<<<2 * N + SUMW_CTAS, 256>>>(logits, gold, mask, weight, out, C4, C, N);
}

// round 12
// speedup vs baseline: 1.2777x; 1.2777x over previous
#include <cuda_runtime.h>
#include <cuda_bf16.h>

// Seq2SeqLoss: label-smoothed weighted cross-entropy, mean over masked rows.
// Harness canonical dtypes:
//   [0] outputs  f32 [B*S*C] = 131072000
//   [1] gold     i32 [B*S]   = 4096
//   [2] mask     i32 [B*S]   = 4096
//   [3] weight   f32 [C]     = 32000
// output: f32 scalar
//
// Sum factorization: with lse_r = log(sum_c exp(x_rc)), dd_r = sum_c w_c x_rc,
//   sum_r loss_r = uniform*(sumW*Σlse − Σdd) + (conf−uniform)*Σ w_g (lse − x_g)
//
// R10 (90us) was wave-quantized: makespan = ceil(4096/1184)=4 quanta of 22.6us.
// R11 (half-row CTAs) proved small CTAs add idle, not speed.
// R12: PERSISTENT grid of exactly one wave (1216 CTAs on GB300's 152 SMs),
// each CTA grid-strides over 3-4 full rows. Unequal static work self-balances
// through the shared DRAM pool (retiring CTAs donate bandwidth to stragglers).
// Streaming loop body is byte-identical to the proven version.

#define SMOOTHING 0.1f
#define EPSILON   1e-8f
#define SUMW_CTAS 8
#define GRID_CTAS 1216    // 152 SMs x 8 CTAs (256 thr, 32 regs) = one full wave

__device__ float        g_sumw;
__device__ float        g_lse_acc;
__device__ float        g_dot_acc;
__device__ float        g_gold_acc;
__device__ float        g_mask_acc;
__device__ unsigned int g_done;

// All-FMA exp (no MUFU): exp(x) = 2^(x*log2e), magic-number round,
// degree-5 poly for 2^f on [-0.5,0.5] (rel err ~2.4e-6), exponent splice.
__device__ __forceinline__ float fexp(float x) {
    float t = x * 1.4426950408889634f;
    t = fminf(fmaxf(t, -126.0f), 126.0f);
    float r = t + 12582912.0f;
    int   eb = __float_as_int(r) << 23;
    float nf = r - 12582912.0f;
    float f  = t - nf;
    float p  = 1.3333558146428443e-3f;
    p = fmaf(p, f, 9.6181291076284772e-3f);
    p = fmaf(p, f, 5.5504108664821580e-2f);
    p = fmaf(p, f, 2.4022650695910072e-1f);
    p = fmaf(p, f, 6.9314718055994531e-1f);
    p = fmaf(p, f, 1.0f);
    return __int_as_float(__float_as_int(p) + eb);
}

__device__ __forceinline__ float warp_sum(float v) {
    #pragma unroll
    for (int o = 16; o > 0; o >>= 1) v += __shfl_xor_sync(0xffffffffu, v, o);
    return v;
}

// acq_rel counter bump: release orders this CTA's prior REDs; acquire on the
// final bump makes all CTAs' REDs visible. No fences -> no CCTL.IVALL L1 flush.
__device__ __forceinline__ unsigned int atom_inc_acqrel(unsigned int* p) {
    unsigned int old;
    asm volatile("atom.acq_rel.gpu.global.add.u32 %0, [%1], 1;"
                 : "=r"(old) : "l"(p) : "memory");
    return old;
}

__device__ __forceinline__ void arrive_and_maybe_finalize(
    float* __restrict__ out, int C, unsigned int total_ctas)
{
    unsigned int prev = atom_inc_acqrel(&g_done);
    if (prev == total_ctas - 1u) {
        float sumw = __ldcg(&g_sumw);
        float lse  = __ldcg(&g_lse_acc);
        float dot  = __ldcg(&g_dot_acc);
        float gld  = __ldcg(&g_gold_acc);
        float msk  = __ldcg(&g_mask_acc);

        const float uniform = SMOOTHING / (float)(C - 1);
        const float conf    = 1.0f - SMOOTHING;
        const float cmu     = conf - uniform;
        float loss_sum = uniform * fmaf(sumw, lse, -dot) + cmu * gld;
        out[0] = loss_sum / (msk + EPSILON);

        // reset for next graph replay (deterministic)
        __stcg(&g_sumw, 0.0f);
        __stcg(&g_lse_acc, 0.0f);
        __stcg(&g_dot_acc, 0.0f);
        __stcg(&g_gold_acc, 0.0f);
        __stcg(&g_mask_acc, 0.0f);
        unsigned int z = 0u;
        asm volatile("st.global.cg.u32 [%0], %1;" :: "l"(&g_done), "r"(z) : "memory");
    }
}

// Persistent grid: GRID_CTAS CTAs. CTAs 0..7 first sum a weight slice into
// g_sumw, then every CTA grid-strides over rows. Per-row epilogue is
// double-buffered so thread 0's atomic chain overlaps the next row's stream.
__global__ __launch_bounds__(256) void row_loss_kernel(
    const float* __restrict__ logits,
    const int*   __restrict__ gold,
    const int*   __restrict__ mask,
    const float* __restrict__ weight,
    float* __restrict__ out,
    int C4, int C, int N)
{
    const int bid = blockIdx.x;
    const int tid = threadIdx.x;
    const float4* wp = reinterpret_cast<const float4*>(weight);

    __shared__ float sh_s[2][8], sh_d[2][8];
    __shared__ int   sh_row[2];

    // ---- sumW slice (CTAs 0..7 only, before row work) ----
    if (bid < SUMW_CTAS) {
        const int per = (C4 + SUMW_CTAS - 1) / SUMW_CTAS;
        const int lo  = bid * per;
        const int hi  = min(lo + per, C4);
        float w = 0.0f;
        for (int i = lo + tid; i < hi; i += 256) {
            float4 v = __ldg(wp + i);
            w += v.x + v.y + v.z + v.w;
        }
        w = warp_sum(w);
        if ((tid & 31) == 0) sh_s[0][tid >> 5] = w;
        __syncthreads();
        if (tid == 0) {
            float ww = 0.0f;
            #pragma unroll
            for (int k = 0; k < 8; k++) ww += sh_s[0][k];
            atomicAdd(&g_sumw, ww);
        }
        __syncthreads();
    }

    const int wid = tid >> 5;
    const int lid = tid & 31;

    // ---- persistent row loop ----
    int it = 0;
    for (int row = bid; row < N; row += GRID_CTAS, it++) {
        const float4* lp = reinterpret_cast<const float4*>(logits) + (size_t)row * C4;

        // proven streaming loop body (do not touch)
        float s = 0.0f, d = 0.0f;
        #pragma unroll 4
        for (int i = tid; i < C4; i += 256) {
            float4 x = __ldcs(lp + i);
            float4 w = __ldg(wp + i);
            d = fmaf(x.x, w.x, d);
            d = fmaf(x.y, w.y, d);
            d = fmaf(x.z, w.z, d);
            d = fmaf(x.w, w.w, d);
            s += fexp(x.x);
            s += fexp(x.y);
            s += fexp(x.z);
            s += fexp(x.w);
        }

        const int par = it & 1;
        s = warp_sum(s);
        d = warp_sum(d);
        if (lid == 0) { sh_s[par][wid] = s; sh_d[par][wid] = d; }
        if (tid == 0) sh_row[par] = row;
        __syncthreads();

        // Thread 0 finishes this row while the other warps roll into the next
        // row's stream (different shared buffer parity -> no race; thread 0's
        // reads complete before it reaches the next __syncthreads).
        if (tid == 0) {
            int r = sh_row[par];
            if (mask[r] != 0) {
                float ss = 0.0f, dd = 0.0f;
                #pragma unroll
                for (int k = 0; k < 8; k++) { ss += sh_s[par][k]; dd += sh_d[par][k]; }

                int   g   = gold[r];
                float xg  = __ldg(logits + (size_t)r * C + (size_t)g);
                float wg  = __ldg(weight + g);
                float lse = logf(ss);

                atomicAdd(&g_lse_acc,  lse);            // fire-and-forget REDs
                atomicAdd(&g_dot_acc,  dd);
                atomicAdd(&g_gold_acc, wg * (lse - xg));
                atomicAdd(&g_mask_acc, 1.0f);
            }
        }
    }

    // one arrival per CTA; last of GRID_CTAS finalizes
    if (tid == 0) arrive_and_maybe_finalize(out, C, (unsigned int)GRID_CTAS);
}

extern "C" void kernel_launch(void* const* d_in, const int* in_sizes, int n_in,
                              void* d_out, int out_size)
{
    const float* logits = (const float*)d_in[0];
    const int*   gold   = (const int*)d_in[1];
    const int*   mask   = (const int*)d_in[2];
    const float* weight = (const float*)d_in[3];
    float*       out    = (float*)d_out;

    const int N = in_sizes[1];     // B*S rows
    const int C = in_sizes[3];     // classes
    const int C4 = C / 4;

    row_loss_kernel<<<GRID_CTAS, 256>>>(logits, gold, mask, weight, out, C4, C, N);
}

// round 13
// speedup vs baseline: 1.4954x; 1.1703x over previous
#include <cuda_runtime.h>
#include <cuda_bf16.h>

// Seq2SeqLoss: label-smoothed weighted cross-entropy, mean over masked rows.
// Harness canonical dtypes:
//   [0] outputs  f32 [B*S*C] = 131072000
//   [1] gold     i32 [B*S]   = 4096
//   [2] mask     i32 [B*S]   = 4096
//   [3] weight   f32 [C]     = 32000
// output: f32 scalar
//
// Sum factorization: with lse_r = log(sum_c exp(x_rc)), dd_r = sum_c w_c x_rc,
//   sum_r loss_r = uniform*(sumW*Σlse − Σdd) + (conf−uniform)*Σ w_g (lse − x_g)
//
// R12 failed because regs crept 32->38, dropping occupancy to 6 CTAs/SM and
// turning the "one wave" persistent grid into a ragged 1.33-wave schedule.
// R13: identical structure with __launch_bounds__(256, 8) enforcing the
// 32-reg budget -> true single wave of 1216 CTAs (8 x 152 SMs), each
// grid-striding 3-4 rows; DRAM-pool redistribution compresses the tail.

#define SMOOTHING 0.1f
#define EPSILON   1e-8f
#define SUMW_CTAS 8
#define GRID_CTAS 1216    // 152 SMs x 8 CTAs = exactly one wave at 32 regs

__device__ float        g_sumw;
__device__ float        g_lse_acc;
__device__ float        g_dot_acc;
__device__ float        g_gold_acc;
__device__ float        g_mask_acc;
__device__ unsigned int g_done;

// All-FMA exp (no MUFU): exp(x) = 2^(x*log2e), magic-number round,
// degree-5 poly for 2^f on [-0.5,0.5] (rel err ~2.4e-6), exponent splice.
__device__ __forceinline__ float fexp(float x) {
    float t = x * 1.4426950408889634f;
    t = fminf(fmaxf(t, -126.0f), 126.0f);
    float r = t + 12582912.0f;
    int   eb = __float_as_int(r) << 23;
    float nf = r - 12582912.0f;
    float f  = t - nf;
    float p  = 1.3333558146428443e-3f;
    p = fmaf(p, f, 9.6181291076284772e-3f);
    p = fmaf(p, f, 5.5504108664821580e-2f);
    p = fmaf(p, f, 2.4022650695910072e-1f);
    p = fmaf(p, f, 6.9314718055994531e-1f);
    p = fmaf(p, f, 1.0f);
    return __int_as_float(__float_as_int(p) + eb);
}

__device__ __forceinline__ float warp_sum(float v) {
    #pragma unroll
    for (int o = 16; o > 0; o >>= 1) v += __shfl_xor_sync(0xffffffffu, v, o);
    return v;
}

// acq_rel counter bump: release orders this CTA's prior REDs; acquire on the
// final bump makes all CTAs' REDs visible. No fences -> no CCTL.IVALL L1 flush.
__device__ __forceinline__ unsigned int atom_inc_acqrel(unsigned int* p) {
    unsigned int old;
    asm volatile("atom.acq_rel.gpu.global.add.u32 %0, [%1], 1;"
                 : "=r"(old) : "l"(p) : "memory");
    return old;
}

__device__ __forceinline__ void arrive_and_maybe_finalize(
    float* __restrict__ out, int C, unsigned int total_ctas)
{
    unsigned int prev = atom_inc_acqrel(&g_done);
    if (prev == total_ctas - 1u) {
        float sumw = __ldcg(&g_sumw);
        float lse  = __ldcg(&g_lse_acc);
        float dot  = __ldcg(&g_dot_acc);
        float gld  = __ldcg(&g_gold_acc);
        float msk  = __ldcg(&g_mask_acc);

        const float uniform = SMOOTHING / (float)(C - 1);
        const float conf    = 1.0f - SMOOTHING;
        const float cmu     = conf - uniform;
        float loss_sum = uniform * fmaf(sumw, lse, -dot) + cmu * gld;
        out[0] = loss_sum / (msk + EPSILON);

        // reset for next graph replay (deterministic)
        __stcg(&g_sumw, 0.0f);
        __stcg(&g_lse_acc, 0.0f);
        __stcg(&g_dot_acc, 0.0f);
        __stcg(&g_gold_acc, 0.0f);
        __stcg(&g_mask_acc, 0.0f);
        unsigned int z = 0u;
        asm volatile("st.global.cg.u32 [%0], %1;" :: "l"(&g_done), "r"(z) : "memory");
    }
}

// Persistent single-wave grid. CTAs 0..7 first sum a weight slice into g_sumw,
// then every CTA grid-strides over rows. Per-row epilogue is double-buffered
// so thread 0's atomic chain overlaps the next row's stream.
__global__ __launch_bounds__(256, 8) void row_loss_kernel(
    const float* __restrict__ logits,
    const int*   __restrict__ gold,
    const int*   __restrict__ mask,
    const float* __restrict__ weight,
    float* __restrict__ out,
    int C4, int C, int N)
{
    const int bid = blockIdx.x;
    const int tid = threadIdx.x;
    const float4* wp = reinterpret_cast<const float4*>(weight);

    __shared__ float sh_s[2][8], sh_d[2][8];
    __shared__ int   sh_row[2];

    // ---- sumW slice (CTAs 0..7 only, before row work) ----
    if (bid < SUMW_CTAS) {
        const int per = (C4 + SUMW_CTAS - 1) / SUMW_CTAS;
        const int lo  = bid * per;
        const int hi  = min(lo + per, C4);
        float w = 0.0f;
        for (int i = lo + tid; i < hi; i += 256) {
            float4 v = __ldg(wp + i);
            w += v.x + v.y + v.z + v.w;
        }
        w = warp_sum(w);
        if ((tid & 31) == 0) sh_s[0][tid >> 5] = w;
        __syncthreads();
        if (tid == 0) {
            float ww = 0.0f;
            #pragma unroll
            for (int k = 0; k < 8; k++) ww += sh_s[0][k];
            atomicAdd(&g_sumw, ww);
        }
        __syncthreads();
    }

    const int wid = tid >> 5;
    const int lid = tid & 31;

    // ---- persistent row loop (3-4 rows per CTA) ----
    int it = 0;
    for (int row = bid; row < N; row += GRID_CTAS, it++) {
        const float4* lp = reinterpret_cast<const float4*>(logits) + (size_t)row * C4;

        // proven streaming loop body (do not touch)
        float s = 0.0f, d = 0.0f;
        #pragma unroll 4
        for (int i = tid; i < C4; i += 256) {
            float4 x = __ldcs(lp + i);
            float4 w = __ldg(wp + i);
            d = fmaf(x.x, w.x, d);
            d = fmaf(x.y, w.y, d);
            d = fmaf(x.z, w.z, d);
            d = fmaf(x.w, w.w, d);
            s += fexp(x.x);
            s += fexp(x.y);
            s += fexp(x.z);
            s += fexp(x.w);
        }

        const int par = it & 1;
        s = warp_sum(s);
        d = warp_sum(d);
        if (lid == 0) { sh_s[par][wid] = s; sh_d[par][wid] = d; }
        if (tid == 0) sh_row[par] = row;
        __syncthreads();

        // Thread 0 finishes this row while the other warps roll into the next
        // row's stream (parity buffers make this race-free).
        if (tid == 0) {
            int r = sh_row[par];
            if (mask[r] != 0) {
                float ss = 0.0f, dd = 0.0f;
                #pragma unroll
                for (int k = 0; k < 8; k++) { ss += sh_s[par][k]; dd += sh_d[par][k]; }

                int   g   = gold[r];
                float xg  = __ldg(logits + (size_t)r * C + (size_t)g);
                float wg  = __ldg(weight + g);
                float lse = logf(ss);

                atomicAdd(&g_lse_acc,  lse);            // fire-and-forget REDs
                atomicAdd(&g_dot_acc,  dd);
                atomicAdd(&g_gold_acc, wg * (lse - xg));
                atomicAdd(&g_mask_acc, 1.0f);
            }
        }
    }

    // one arrival per CTA; last of GRID_CTAS finalizes
    if (tid == 0) arrive_and_maybe_finalize(out, C, (unsigned int)GRID_CTAS);
}

extern "C" void kernel_launch(void* const* d_in, const int* in_sizes, int n_in,
                              void* d_out, int out_size)
{
    const float* logits = (const float*)d_in[0];
    const int*   gold   = (const int*)d_in[1];
    const int*   mask   = (const int*)d_in[2];
    const float* weight = (const float*)d_in[3];
    float*       out    = (float*)d_out;

    const int N = in_sizes[1];     // B*S rows
    const int C = in_sizes[3];     // classes
    const int C4 = C / 4;

    row_loss_kernel<<<GRID_CTAS, 256>>>(logits, gold, mask, weight, out, C4, C, N);
}